// round 2
// baseline (speedup 1.0000x reference)
#include <cuda_runtime.h>
#include <math.h>

#define EMBED   256
#define NHEADS  8
#define HDIM    32
#define NPAIRS  16
#define NLEV    4
#define FULL    128
#define KPQ     164
#define MAXQ    2048
#define MAXB    2

// Scratch (device globals; no runtime allocation allowed)
__device__ float g_Kmap[MAXB * NLEV * FULL * FULL * EMBED]; // padded full-res layout
__device__ float g_Vmap[MAXB * NLEV * FULL * FULL * EMBED];
__device__ float g_qrot[MAXQ * EMBED];
__device__ float g_tmp [MAXQ * EMBED];

// ---------------------------------------------------------------------------
// Kernel 1: LayerNorm + Q projection + RoPE.  8 queries per block, 256 threads.
// ---------------------------------------------------------------------------
__global__ __launch_bounds__(256) void qln_kernel(
    const float* __restrict__ query, const float* __restrict__ qpos,
    const float* __restrict__ nw, const float* __restrict__ nb,
    const float* __restrict__ qw, const float* __restrict__ rf, int n_q)
{
    const int t  = threadIdx.x;
    const int n0 = blockIdx.x * 8;
    __shared__ float xs[8][EMBED];
    __shared__ float red[16];

    float val[8];
    #pragma unroll
    for (int r = 0; r < 8; r++) {
        int n = n0 + r;
        val[r] = (n < n_q) ? query[n * EMBED + t] : 0.f;
    }

    // LayerNorm each of the 8 rows
    #pragma unroll
    for (int r = 0; r < 8; r++) {
        float s = val[r], s2 = val[r] * val[r];
        #pragma unroll
        for (int o = 16; o; o >>= 1) {
            s  += __shfl_xor_sync(~0u, s, o);
            s2 += __shfl_xor_sync(~0u, s2, o);
        }
        int w = t >> 5;
        if ((t & 31) == 0) { red[w] = s; red[8 + w] = s2; }
        __syncthreads();
        float sum = 0.f, sum2 = 0.f;
        #pragma unroll
        for (int i = 0; i < 8; i++) { sum += red[i]; sum2 += red[8 + i]; }
        __syncthreads();
        float mean = sum * (1.0f / EMBED);
        float var  = sum2 * (1.0f / EMBED) - mean * mean;
        float inv  = rsqrtf(var + 1e-5f);
        xs[r][t] = (val[r] - mean) * inv * nw[t] + nb[t];
    }
    __syncthreads();

    // Q projection: acc[r] = sum_i xs[r][i] * qw[i][t]
    float acc[8];
    #pragma unroll
    for (int r = 0; r < 8; r++) acc[r] = 0.f;
    #pragma unroll 4
    for (int i = 0; i < EMBED; i++) {
        float w = qw[i * EMBED + t];
        #pragma unroll
        for (int r = 0; r < 8; r++) acc[r] += xs[r][i] * w;
    }
    __syncthreads();
    #pragma unroll
    for (int r = 0; r < 8; r++) xs[r][t] = acc[r];
    __syncthreads();

    // RoPE: pair p = (t%32)/2, angle = p0*f0[p] + p1*f1[p]
    const int p = (t & 31) >> 1;
    const float f0 = rf[p], f1 = rf[NPAIRS + p];
    #pragma unroll
    for (int r = 0; r < 8; r++) {
        int n = n0 + r;
        if (n >= n_q) break;
        float ang = qpos[n * 2 + 0] * f0 + qpos[n * 2 + 1] * f1;
        float sn, cs; sincosf(ang, &sn, &cs);
        float x1 = xs[r][t & ~1], x2 = xs[r][t | 1];
        g_qrot[n * EMBED + t] = ((t & 1) == 0) ? (x1 * cs - x2 * sn)
                                               : (x1 * sn + x2 * cs);
    }
}

// ---------------------------------------------------------------------------
// Kernel 2: K-map / V-map GEMM.  C[r][j] = sum_i feat[r][i] * W[i][j]
// BM=128, BN=64, BK=16, 256 threads, 8x4 microtile.
// blockIdx.z = b*4+l, blockIdx.y = row tile, blockIdx.x: 0-3 -> K (k_w), 4-7 -> V (v_w)
// ---------------------------------------------------------------------------
#define BM 128
#define BN 64
#define BK 16

__global__ __launch_bounds__(256) void kv_gemm(
    const float* __restrict__ fm, const float* __restrict__ kw,
    const float* __restrict__ vw, const int* __restrict__ shp)
{
    const int z = blockIdx.z;
    const int l = z & 3;
    const int H = shp[2 * l], W = shp[2 * l + 1];
    const int S = H * W;
    const int row0 = blockIdx.y * BM;
    if (row0 >= S) return;

    const float* Wt; float* outp; int col0;
    if (blockIdx.x < 4) { Wt = kw; outp = g_Kmap; col0 = blockIdx.x * BN; }
    else                { Wt = vw; outp = g_Vmap; col0 = (blockIdx.x - 4) * BN; }

    __shared__ float As[BK][BM];
    __shared__ float Bs[BK][BN];
    __shared__ int   rowAddr[BM];

    const int tid = threadIdx.x;
    if (tid < BM) {
        int r = row0 + tid;
        rowAddr[tid] = (r < S) ? ((z * FULL + r / W) * FULL + (r % W)) * EMBED : -1;
    }
    __syncthreads();

    float acc[8][4];
    #pragma unroll
    for (int i = 0; i < 8; i++)
        #pragma unroll
        for (int j = 0; j < 4; j++) acc[i][j] = 0.f;

    const int tr = tid >> 4;     // 0..15 -> 8 rows each
    const int tc = tid & 15;     // 0..15 -> 4 cols each

    for (int k0 = 0; k0 < EMBED; k0 += BK) {
        // Load A tile (128 x 16), float4 per thread x2
        #pragma unroll
        for (int rr = 0; rr < 2; rr++) {
            int idx  = rr * 256 + tid;
            int arow = idx & 127;
            int ak   = (idx >> 7) * 4;
            int ra   = rowAddr[arow];
            float4 av = make_float4(0.f, 0.f, 0.f, 0.f);
            if (ra >= 0) av = *(const float4*)(fm + ra + k0 + ak);
            As[ak + 0][arow] = av.x;
            As[ak + 1][arow] = av.y;
            As[ak + 2][arow] = av.z;
            As[ak + 3][arow] = av.w;
        }
        // Load B tile (16 x 64)
        {
            int bk = tid >> 4;
            int bn = (tid & 15) * 4;
            *(float4*)&Bs[bk][bn] = *(const float4*)(Wt + (k0 + bk) * EMBED + col0 + bn);
        }
        __syncthreads();
        #pragma unroll
        for (int kk = 0; kk < BK; kk++) {
            float4 a0 = *(const float4*)&As[kk][tr * 8];
            float4 a1 = *(const float4*)&As[kk][tr * 8 + 4];
            float4 b  = *(const float4*)&Bs[kk][tc * 4];
            float am[8] = {a0.x, a0.y, a0.z, a0.w, a1.x, a1.y, a1.z, a1.w};
            float bm[4] = {b.x, b.y, b.z, b.w};
            #pragma unroll
            for (int i = 0; i < 8; i++)
                #pragma unroll
                for (int j = 0; j < 4; j++)
                    acc[i][j] += am[i] * bm[j];
        }
        __syncthreads();
    }

    #pragma unroll
    for (int i = 0; i < 8; i++) {
        int mr = tr * 8 + i;
        int ra = rowAddr[mr];
        if (ra >= 0) {
            float4 v = make_float4(acc[i][0], acc[i][1], acc[i][2], acc[i][3]);
            *(float4*)(outp + ra + col0 + tc * 4) = v;
        }
    }
}

// ---------------------------------------------------------------------------
// Kernel 3: attention. One block per query, 256 threads. Warp w == head w.
// ---------------------------------------------------------------------------
__global__ __launch_bounds__(256) void attn_kernel(
    const float* __restrict__ qpos, const float* __restrict__ rf,
    const int* __restrict__ boff, int n_off, const int* __restrict__ shp)
{
    const int n = blockIdx.x;
    const int t = threadIdx.x;

    __shared__ float F[48];
    __shared__ int   rowOff[KPQ];
    __shared__ float ksp0[KPQ], ksp1[KPQ], klvl[KPQ];
    __shared__ float logits[NHEADS * KPQ];

    if (t < 48) F[t] = rf[t];

    if (t < KPQ) {
        int k = t, l, base;
        if      (k < 9)  { l = 0; base = 0;  }
        else if (k < 34) { l = 1; base = 9;  }
        else if (k < 83) { l = 2; base = 34; }
        else             { l = 3; base = 83; }
        int s = 2 * l + 3, half = l + 1;
        int j = k - base;
        int o0 = j / s - half, o1 = j % s - half;
        int H = shp[2 * l], W = shp[2 * l + 1];
        int maxH = 0, maxW = 0;
        #pragma unroll
        for (int li = 0; li < NLEV; li++) {
            maxH = max(maxH, shp[2 * li]);
            maxW = max(maxW, shp[2 * li + 1]);
        }
        float p0 = qpos[n * 2 + 0], p1 = qpos[n * 2 + 1];
        int c0 = (int)floorf(p0 * ((float)H / (float)maxH));
        int c1 = (int)floorf(p1 * ((float)W / (float)maxW));
        int i0 = c0 + o0, i1 = c1 + o1;
        bool valid = (i0 >= 0) && (i0 < H) && (i1 >= 0) && (i1 < W);
        int b = 0;
        for (int ii = 1; ii < n_off - 1; ii++) if (n >= boff[ii]) b = ii;
        rowOff[t] = valid ? (((b * NLEV + l) * FULL + i0) * FULL + i1) * EMBED : -1;
        ksp0[t] = (i0 + 0.5f) * ((float)maxH / (float)H);
        ksp1[t] = (i1 + 0.5f) * ((float)maxW / (float)W);
        klvl[t] = (float)l;
    }
    __syncthreads();

    const int h = t >> 5, lane = t & 31, p = lane >> 1;
    const float qv = g_qrot[n * EMBED + t];
    const float f0 = F[p], f1 = F[NPAIRS + p], f2 = F[2 * NPAIRS + p];

    // Logits
    for (int k = 0; k < KPQ; k++) {
        int ro = rowOff[k];
        float contrib = 0.f;
        if (ro >= 0) {
            float kv = g_Kmap[ro + t];
            float pn = __shfl_xor_sync(~0u, kv, 1);
            float ang = ksp0[k] * f0 + ksp1[k] * f1 + klvl[k] * f2;
            float sn, cs; sincosf(ang, &sn, &cs);
            float kr = ((lane & 1) == 0) ? (kv * cs - pn * sn)
                                         : (pn * sn + kv * cs);
            contrib = qv * kr;
        }
        #pragma unroll
        for (int o = 16; o; o >>= 1) contrib += __shfl_xor_sync(~0u, contrib, o);
        if (lane == 0)
            logits[h * KPQ + k] = (ro >= 0) ? contrib * 0.17677669529663687f : -1e9f;
    }
    __syncwarp();

    // Softmax (per warp / head)
    float m = -1e30f;
    for (int k = lane; k < KPQ; k += 32) m = fmaxf(m, logits[h * KPQ + k]);
    #pragma unroll
    for (int o = 16; o; o >>= 1) m = fmaxf(m, __shfl_xor_sync(~0u, m, o));
    float ssum = 0.f;
    for (int k = lane; k < KPQ; k += 32) {
        float e = __expf(logits[h * KPQ + k] - m);
        logits[h * KPQ + k] = e;
        ssum += e;
    }
    #pragma unroll
    for (int o = 16; o; o >>= 1) ssum += __shfl_xor_sync(~0u, ssum, o);
    __syncwarp();
    const float inv = 1.0f / ssum;

    // Weighted V gather
    float acc = 0.f;
    for (int k = 0; k < KPQ; k++) {
        int ro = rowOff[k];
        if (ro >= 0) acc += logits[h * KPQ + k] * g_Vmap[ro + t];
    }
    g_tmp[n * EMBED + t] = acc * inv;
}

// ---------------------------------------------------------------------------
// Kernel 4: output projection + residual.  8 queries per block.
// ---------------------------------------------------------------------------
__global__ __launch_bounds__(256) void out_proj_kernel(
    const float* __restrict__ query, const float* __restrict__ ow,
    float* __restrict__ out, int n_q)
{
    const int t  = threadIdx.x;
    const int n0 = blockIdx.x * 8;
    __shared__ float xs[8][EMBED];

    #pragma unroll
    for (int r = 0; r < 8; r++) {
        int n = n0 + r;
        xs[r][t] = (n < n_q) ? g_tmp[n * EMBED + t] : 0.f;
    }
    __syncthreads();

    float acc[8];
    #pragma unroll
    for (int r = 0; r < 8; r++) acc[r] = 0.f;
    #pragma unroll 4
    for (int i = 0; i < EMBED; i++) {
        float w = ow[i * EMBED + t];
        #pragma unroll
        for (int r = 0; r < 8; r++) acc[r] += xs[r][i] * w;
    }
    #pragma unroll
    for (int r = 0; r < 8; r++) {
        int n = n0 + r;
        if (n < n_q) out[n * EMBED + t] = acc[r] + query[n * EMBED + t];
    }
}

// ---------------------------------------------------------------------------
extern "C" void kernel_launch(void* const* d_in, const int* in_sizes, int n_in,
                              void* d_out, int out_size)
{
    const float* query = (const float*)d_in[0];
    const float* qpos  = (const float*)d_in[1];
    const float* fm    = (const float*)d_in[2];
    const float* nw    = (const float*)d_in[3];
    const float* nb    = (const float*)d_in[4];
    const float* qw    = (const float*)d_in[5];
    const float* kw    = (const float*)d_in[6];
    const float* vw    = (const float*)d_in[7];
    const float* ow    = (const float*)d_in[8];
    const float* rf    = (const float*)d_in[9];
    const int*   boff  = (const int*)d_in[10];
    const int*   shp   = (const int*)d_in[11];

    int n_q   = in_sizes[0] / EMBED;
    int n_off = in_sizes[10];
    int batch = n_off - 1;
    float* out = (float*)d_out;

    int qblocks = (n_q + 7) / 8;
    qln_kernel<<<qblocks, 256>>>(query, qpos, nw, nb, qw, rf, n_q);
    kv_gemm<<<dim3(8, (FULL * FULL + BM - 1) / BM, batch * NLEV), 256>>>(fm, kw, vw, shp);
    attn_kernel<<<n_q, 256>>>(qpos, rf, boff, n_off, shp);
    out_proj_kernel<<<qblocks, 256>>>(query, ow, out, n_q);
}

// round 4
// speedup vs baseline: 1.6455x; 1.6455x over previous
#include <cuda_runtime.h>
#include <math.h>

#define EMBED   256
#define NHEADS  8
#define HDIM    32
#define NPAIRS  16
#define NLEV    4
#define FULL    128
#define KPQ     164
#define MAXQ    2048
#define MAXB    2
#define NCELLS  (MAXB * NLEV * FULL * FULL)   // 131072 padded cells

// Scratch (device globals; no runtime allocation allowed)
__device__ float g_Kmap[NCELLS * EMBED];
__device__ float g_Vmap[NCELLS * EMBED];
__device__ float g_qrot[MAXQ * EMBED];
__device__ float g_tmp [MAXQ * EMBED];
__device__ int   g_mask[NCELLS];
__device__ int   g_rows[NCELLS];
__device__ int   g_nactive;
__device__ int   g_rowOff[MAXQ * KPQ];
__device__ float g_ksp0[MAXQ * KPQ];
__device__ float g_ksp1[MAXQ * KPQ];

// ---------------------------------------------------------------------------
// Kernel 0: zero mask + counter
// ---------------------------------------------------------------------------
__global__ void zero_kernel()
{
    int i = blockIdx.x * blockDim.x + threadIdx.x;
    if (i < NCELLS) g_mask[i] = 0;
    if (i == 0) g_nactive = 0;
}

// ---------------------------------------------------------------------------
// Kernel 0b: per-(query,key) geometry + mark touched cells
// ---------------------------------------------------------------------------
__global__ void prep_kernel(const float* __restrict__ qpos,
                            const int* __restrict__ boff, int n_off,
                            const int* __restrict__ shp, int n_q)
{
    int n = blockIdx.x, t = threadIdx.x;
    if (n >= n_q || t >= KPQ) return;
    int l, base;
    if      (t < 9)  { l = 0; base = 0;  }
    else if (t < 34) { l = 1; base = 9;  }
    else if (t < 83) { l = 2; base = 34; }
    else             { l = 3; base = 83; }
    int s = 2 * l + 3, half = l + 1, j = t - base;
    int o0 = j / s - half, o1 = j % s - half;
    int H = shp[2 * l], W = shp[2 * l + 1];
    int maxH = 0, maxW = 0;
    #pragma unroll
    for (int li = 0; li < NLEV; li++) {
        maxH = max(maxH, shp[2 * li]);
        maxW = max(maxW, shp[2 * li + 1]);
    }
    float p0 = qpos[n * 2 + 0], p1 = qpos[n * 2 + 1];
    int c0 = (int)floorf(p0 * ((float)H / (float)maxH));
    int c1 = (int)floorf(p1 * ((float)W / (float)maxW));
    int i0 = c0 + o0, i1 = c1 + o1;
    bool valid = (i0 >= 0) && (i0 < H) && (i1 >= 0) && (i1 < W);
    int b = 0;
    for (int ii = 1; ii < n_off - 1; ii++) if (n >= boff[ii]) b = ii;
    int cell = ((b * NLEV + l) * FULL + i0) * FULL + i1;
    g_rowOff[n * KPQ + t] = valid ? cell * EMBED : -1;
    if (valid) g_mask[cell] = 1;
    g_ksp0[n * KPQ + t] = (i0 + 0.5f) * ((float)maxH / (float)H);
    g_ksp1[n * KPQ + t] = (i1 + 0.5f) * ((float)maxW / (float)W);
}

// ---------------------------------------------------------------------------
// Kernel 0c: compact marked cells into active row list
// ---------------------------------------------------------------------------
__global__ void compact_kernel()
{
    int i = blockIdx.x * blockDim.x + threadIdx.x;
    if (i < NCELLS && g_mask[i]) {
        int p = atomicAdd(&g_nactive, 1);
        g_rows[p] = i;
    }
}

// ---------------------------------------------------------------------------
// Kernel 1: LayerNorm + Q projection + RoPE.  8 queries per block.
// ---------------------------------------------------------------------------
__global__ __launch_bounds__(256) void qln_kernel(
    const float* __restrict__ query, const float* __restrict__ qpos,
    const float* __restrict__ nw, const float* __restrict__ nb,
    const float* __restrict__ qw, const float* __restrict__ rf, int n_q)
{
    const int t  = threadIdx.x;
    const int n0 = blockIdx.x * 8;
    __shared__ float xs[8][EMBED];
    __shared__ float red[16];

    float val[8];
    #pragma unroll
    for (int r = 0; r < 8; r++) {
        int n = n0 + r;
        val[r] = (n < n_q) ? query[n * EMBED + t] : 0.f;
    }
    #pragma unroll
    for (int r = 0; r < 8; r++) {
        float s = val[r], s2 = val[r] * val[r];
        #pragma unroll
        for (int o = 16; o; o >>= 1) {
            s  += __shfl_xor_sync(~0u, s, o);
            s2 += __shfl_xor_sync(~0u, s2, o);
        }
        int w = t >> 5;
        if ((t & 31) == 0) { red[w] = s; red[8 + w] = s2; }
        __syncthreads();
        float sum = 0.f, sum2 = 0.f;
        #pragma unroll
        for (int i = 0; i < 8; i++) { sum += red[i]; sum2 += red[8 + i]; }
        __syncthreads();
        float mean = sum * (1.0f / EMBED);
        float var  = sum2 * (1.0f / EMBED) - mean * mean;
        float inv  = rsqrtf(var + 1e-5f);
        xs[r][t] = (val[r] - mean) * inv * nw[t] + nb[t];
    }
    __syncthreads();

    float acc[8];
    #pragma unroll
    for (int r = 0; r < 8; r++) acc[r] = 0.f;
    #pragma unroll 8
    for (int i = 0; i < EMBED; i++) {
        float w = qw[i * EMBED + t];
        #pragma unroll
        for (int r = 0; r < 8; r++) acc[r] += xs[r][i] * w;
    }
    __syncthreads();
    #pragma unroll
    for (int r = 0; r < 8; r++) xs[r][t] = acc[r];
    __syncthreads();

    const int p = (t & 31) >> 1;
    const float f0 = rf[p], f1 = rf[NPAIRS + p];
    #pragma unroll
    for (int r = 0; r < 8; r++) {
        int n = n0 + r;
        if (n >= n_q) break;
        float ang = qpos[n * 2 + 0] * f0 + qpos[n * 2 + 1] * f1;
        float sn, cs; __sincosf(ang, &sn, &cs);
        float x1 = xs[r][t & ~1], x2 = xs[r][t | 1];
        g_qrot[n * EMBED + t] = ((t & 1) == 0) ? (x1 * cs - x2 * sn)
                                               : (x1 * sn + x2 * cs);
    }
}

// ---------------------------------------------------------------------------
// Kernel 2: K/V GEMM over compacted active rows.
// BM=128, BN=128, BK=8, 256 threads, 8x8 microtile.
// grid.x: 0-1 -> K (col 0/128), 2-3 -> V (col 0/128). grid.y: row tiles.
// ---------------------------------------------------------------------------
#define BM 128
#define BN 128
#define BK 8

__global__ __launch_bounds__(256, 2) void kv_gemm(
    const float* __restrict__ fm, const float* __restrict__ kw,
    const float* __restrict__ vw)
{
    const int nact = g_nactive;
    const int row0 = blockIdx.y * BM;
    if (row0 >= nact) return;

    const int bx = blockIdx.x;
    const float* Wt = (bx < 2) ? kw : vw;
    float* outp = (bx < 2) ? g_Kmap : g_Vmap;
    const int col0 = (bx & 1) * BN;

    __shared__ float As[BK][BM];
    __shared__ float Bs[BK][BN];
    __shared__ int   rowA[BM];

    const int tid = threadIdx.x;
    if (tid < BM) {
        int r = row0 + tid;
        rowA[tid] = (r < nact) ? g_rows[r] * EMBED : -1;
    }
    __syncthreads();

    float acc[8][8];
    #pragma unroll
    for (int i = 0; i < 8; i++)
        #pragma unroll
        for (int j = 0; j < 8; j++) acc[i][j] = 0.f;

    const int tr = tid >> 4;        // 0..15 row group
    const int tc = tid & 15;        // 0..15 col group
    const int am = tid >> 1;        // A load: row 0..127
    const int ak = (tid & 1) * 4;   // A load: k 0 or 4
    const int bk = tid >> 5;        // B load: k 0..7
    const int bn = (tid & 31) * 4;  // B load: col

    #pragma unroll 1
    for (int k0 = 0; k0 < EMBED; k0 += BK) {
        int ra = rowA[am];
        float4 av = make_float4(0.f, 0.f, 0.f, 0.f);
        if (ra >= 0) av = *(const float4*)(fm + ra + k0 + ak);
        As[ak + 0][am] = av.x;
        As[ak + 1][am] = av.y;
        As[ak + 2][am] = av.z;
        As[ak + 3][am] = av.w;
        *(float4*)&Bs[bk][bn] = *(const float4*)(Wt + (k0 + bk) * EMBED + col0 + bn);
        __syncthreads();
        #pragma unroll
        for (int kk = 0; kk < BK; kk++) {
            float4 a0 = *(const float4*)&As[kk][tr * 8];
            float4 a1 = *(const float4*)&As[kk][tr * 8 + 4];
            float4 b0 = *(const float4*)&Bs[kk][tc * 8];
            float4 b1 = *(const float4*)&Bs[kk][tc * 8 + 4];
            float am8[8] = {a0.x, a0.y, a0.z, a0.w, a1.x, a1.y, a1.z, a1.w};
            float bm8[8] = {b0.x, b0.y, b0.z, b0.w, b1.x, b1.y, b1.z, b1.w};
            #pragma unroll
            for (int i = 0; i < 8; i++)
                #pragma unroll
                for (int j = 0; j < 8; j++)
                    acc[i][j] += am8[i] * bm8[j];
        }
        __syncthreads();
    }

    #pragma unroll
    for (int i = 0; i < 8; i++) {
        int ra = rowA[tr * 8 + i];
        if (ra >= 0) {
            float* dst = outp + ra + col0 + tc * 8;
            *(float4*)(dst)     = make_float4(acc[i][0], acc[i][1], acc[i][2], acc[i][3]);
            *(float4*)(dst + 4) = make_float4(acc[i][4], acc[i][5], acc[i][6], acc[i][7]);
        }
    }
}

// ---------------------------------------------------------------------------
// Kernel 3: attention. One block per query, 256 threads. Warp w == head w.
// ---------------------------------------------------------------------------
__global__ __launch_bounds__(256) void attn_kernel(const float* __restrict__ rf)
{
    const int n = blockIdx.x;
    const int t = threadIdx.x;

    __shared__ float F[48];
    __shared__ int   rowOff[KPQ];
    __shared__ float ksp0[KPQ], ksp1[KPQ], klvl[KPQ];
    __shared__ float csT[KPQ * NPAIRS];
    __shared__ float snT[KPQ * NPAIRS];
    __shared__ float logits[NHEADS * KPQ];

    if (t < 48) F[t] = rf[t];
    if (t < KPQ) {
        rowOff[t] = g_rowOff[n * KPQ + t];
        ksp0[t]   = g_ksp0[n * KPQ + t];
        ksp1[t]   = g_ksp1[n * KPQ + t];
        int l;
        if      (t < 9)  l = 0;
        else if (t < 34) l = 1;
        else if (t < 83) l = 2;
        else             l = 3;
        klvl[t] = (float)l;
    }
    __syncthreads();

    // Angle tables via fast sincos
    for (int idx = t; idx < KPQ * NPAIRS; idx += 256) {
        int k = idx >> 4, p = idx & 15;
        float ang = ksp0[k] * F[p] + ksp1[k] * F[NPAIRS + p] + klvl[k] * F[2 * NPAIRS + p];
        float sn, cs; __sincosf(ang, &sn, &cs);
        csT[idx] = cs; snT[idx] = sn;
    }
    __syncthreads();

    const int h = t >> 5, lane = t & 31, p = lane >> 1;
    const float qv = g_qrot[n * EMBED + t];
    const bool even = (lane & 1) == 0;

    for (int k = 0; k < KPQ; k++) {
        int ro = rowOff[k];
        if (ro >= 0) {
            float kv = g_Kmap[ro + t];
            float pn = __shfl_xor_sync(~0u, kv, 1);
            float cs = csT[k * NPAIRS + p];
            float sn = snT[k * NPAIRS + p];
            float kr = even ? (kv * cs - pn * sn) : (pn * sn + kv * cs);
            float c = qv * kr;
            #pragma unroll
            for (int o = 16; o; o >>= 1) c += __shfl_xor_sync(~0u, c, o);
            if (lane == 0) logits[h * KPQ + k] = c * 0.17677669529663687f;
        } else {
            if (lane == 0) logits[h * KPQ + k] = -1e9f;
        }
    }
    __syncwarp();

    float m = -1e30f;
    for (int k = lane; k < KPQ; k += 32) m = fmaxf(m, logits[h * KPQ + k]);
    #pragma unroll
    for (int o = 16; o; o >>= 1) m = fmaxf(m, __shfl_xor_sync(~0u, m, o));
    float ssum = 0.f;
    for (int k = lane; k < KPQ; k += 32) {
        float e = __expf(logits[h * KPQ + k] - m);
        logits[h * KPQ + k] = e;
        ssum += e;
    }
    #pragma unroll
    for (int o = 16; o; o >>= 1) ssum += __shfl_xor_sync(~0u, ssum, o);
    __syncwarp();
    const float inv = 1.0f / ssum;

    float acc = 0.f;
    for (int k = 0; k < KPQ; k++) {
        int ro = rowOff[k];
        if (ro >= 0) acc += logits[h * KPQ + k] * g_Vmap[ro + t];
    }
    g_tmp[n * EMBED + t] = acc * inv;
}

// ---------------------------------------------------------------------------
// Kernel 4: output projection + residual.
// ---------------------------------------------------------------------------
__global__ __launch_bounds__(256) void out_proj_kernel(
    const float* __restrict__ query, const float* __restrict__ ow,
    float* __restrict__ out, int n_q)
{
    const int t  = threadIdx.x;
    const int n0 = blockIdx.x * 8;
    __shared__ float xs[8][EMBED];

    #pragma unroll
    for (int r = 0; r < 8; r++) {
        int n = n0 + r;
        xs[r][t] = (n < n_q) ? g_tmp[n * EMBED + t] : 0.f;
    }
    __syncthreads();

    float acc[8];
    #pragma unroll
    for (int r = 0; r < 8; r++) acc[r] = 0.f;
    #pragma unroll 8
    for (int i = 0; i < EMBED; i++) {
        float w = ow[i * EMBED + t];
        #pragma unroll
        for (int r = 0; r < 8; r++) acc[r] += xs[r][i] * w;
    }
    #pragma unroll
    for (int r = 0; r < 8; r++) {
        int n = n0 + r;
        if (n < n_q) out[n * EMBED + t] = acc[r] + query[n * EMBED + t];
    }
}

// ---------------------------------------------------------------------------
extern "C" void kernel_launch(void* const* d_in, const int* in_sizes, int n_in,
                              void* d_out, int out_size)
{
    const float* query = (const float*)d_in[0];
    const float* qpos  = (const float*)d_in[1];
    const float* fm    = (const float*)d_in[2];
    const float* nw    = (const float*)d_in[3];
    const float* nb    = (const float*)d_in[4];
    const float* qw    = (const float*)d_in[5];
    const float* kw    = (const float*)d_in[6];
    const float* vw    = (const float*)d_in[7];
    const float* ow    = (const float*)d_in[8];
    const float* rf    = (const float*)d_in[9];
    const int*   boff  = (const int*)d_in[10];
    const int*   shp   = (const int*)d_in[11];

    int n_q   = in_sizes[0] / EMBED;
    int n_off = in_sizes[10];
    float* out = (float*)d_out;

    int qblocks = (n_q + 7) / 8;
    zero_kernel<<<(NCELLS + 255) / 256, 256>>>();
    prep_kernel<<<n_q, 192>>>(qpos, boff, n_off, shp, n_q);
    compact_kernel<<<(NCELLS + 255) / 256, 256>>>();
    qln_kernel<<<qblocks, 256>>>(query, qpos, nw, nb, qw, rf, n_q);
    kv_gemm<<<dim3(4, (2 * 21760 + BM - 1) / BM), 256>>>(fm, kw, vw);
    attn_kernel<<<n_q, 256>>>(rf);
    out_proj_kernel<<<qblocks, 256>>>(query, ow, out, n_q);
}

// round 10
// speedup vs baseline: 2.1511x; 1.3072x over previous
#include <cuda_runtime.h>
#include <cuda_bf16.h>
#include <cstdint>
#include <math.h>

#define EMBED   256
#define NHEADS  8
#define HDIM    32
#define NPAIRS  16
#define NLEV    4
#define FULL    128
#define KPQ     164
#define MAXQ    2048
#define MAXB    2
#define NCELLS  (MAXB * NLEV * FULL * FULL)
#define MAXROWS 43520
#define GP      40
#define QR      4

// Scratch (device globals; no runtime allocation allowed)
__device__ float g_Kmap[NCELLS * EMBED];
__device__ float g_Vmap[NCELLS * EMBED];
__device__ float g_qrot[MAXQ * EMBED];
__device__ float g_tmp [MAXQ * EMBED];
__device__ int   g_mask[NCELLS];
__device__ int   g_rows[NCELLS];
__device__ int   g_nactive;
__device__ int   g_rowOff[MAXQ * KPQ];
__device__ float g_ksp0[MAXQ * KPQ];
__device__ float g_ksp1[MAXQ * KPQ];
__device__ __nv_bfloat16 g_Ah[MAXROWS * EMBED];
__device__ __nv_bfloat16 g_Al[MAXROWS * EMBED];
__device__ __nv_bfloat16 g_WTh[2 * EMBED * EMBED];
__device__ __nv_bfloat16 g_WTl[2 * EMBED * EMBED];

// ---------------------------------------------------------------------------
// mma helpers
// ---------------------------------------------------------------------------
__device__ __forceinline__ unsigned smem_u32(const void* p)
{
    return (unsigned)__cvta_generic_to_shared(p);
}

__device__ __forceinline__ void ldm4(unsigned* r, unsigned a)
{
    asm volatile("ldmatrix.sync.aligned.m8n8.x4.shared.b16 {%0,%1,%2,%3}, [%4];"
        : "=r"(r[0]), "=r"(r[1]), "=r"(r[2]), "=r"(r[3]) : "r"(a));
}

__device__ __forceinline__ void mma16816(float* d, const unsigned* a, const unsigned* b)
{
    asm volatile("mma.sync.aligned.m16n8k16.row.col.f32.bf16.bf16.f32 "
        "{%0,%1,%2,%3}, {%4,%5,%6,%7}, {%8,%9}, {%0,%1,%2,%3};"
        : "+f"(d[0]), "+f"(d[1]), "+f"(d[2]), "+f"(d[3])
        : "r"(a[0]), "r"(a[1]), "r"(a[2]), "r"(a[3]), "r"(b[0]), "r"(b[1]));
}

// ---------------------------------------------------------------------------
__global__ void zero_kernel()
{
    int i = blockIdx.x * blockDim.x + threadIdx.x;
    if (i < NCELLS) { g_mask[i] = 0; }
    if (i == 0) { g_nactive = 0; }
}

// ---------------------------------------------------------------------------
__global__ void prep_kernel(const float* __restrict__ qpos,
                            const int* __restrict__ boff, int n_off,
                            const int* __restrict__ shp, int n_q)
{
    int n = blockIdx.x, t = threadIdx.x;
    if (n >= n_q || t >= KPQ) { return; }
    int l, base;
    if      (t < 9)  { l = 0; base = 0;  }
    else if (t < 34) { l = 1; base = 9;  }
    else if (t < 83) { l = 2; base = 34; }
    else             { l = 3; base = 83; }
    int s = 2 * l + 3, half = l + 1, j = t - base;
    int o0 = j / s - half, o1 = j % s - half;
    int H = shp[2 * l], W = shp[2 * l + 1];
    int maxH = 0, maxW = 0;
    for (int li = 0; li < NLEV; li++) {
        maxH = max(maxH, shp[2 * li]);
        maxW = max(maxW, shp[2 * li + 1]);
    }
    float p0 = qpos[n * 2 + 0], p1 = qpos[n * 2 + 1];
    int c0 = (int)floorf(p0 * ((float)H / (float)maxH));
    int c1 = (int)floorf(p1 * ((float)W / (float)maxW));
    int i0 = c0 + o0, i1 = c1 + o1;
    bool valid = (i0 >= 0) && (i0 < H) && (i1 >= 0) && (i1 < W);
    int b = 0;
    for (int ii = 1; ii < n_off - 1; ii++) {
        if (n >= boff[ii]) { b = ii; }
    }
    int cell = ((b * NLEV + l) * FULL + i0) * FULL + i1;
    g_rowOff[n * KPQ + t] = valid ? cell * EMBED : -1;
    if (valid) { g_mask[cell] = 1; }
    g_ksp0[n * KPQ + t] = (i0 + 0.5f) * ((float)maxH / (float)H);
    g_ksp1[n * KPQ + t] = (i1 + 0.5f) * ((float)maxW / (float)W);
}

// ---------------------------------------------------------------------------
__global__ void compact_kernel()
{
    int i = blockIdx.x * blockDim.x + threadIdx.x;
    if (i < NCELLS && g_mask[i]) {
        int p = atomicAdd(&g_nactive, 1);
        g_rows[p] = i;
    }
}

// ---------------------------------------------------------------------------
// convert weights to transposed hi/lo bf16
// ---------------------------------------------------------------------------
__global__ void convert_w_kernel(const float* __restrict__ kw,
                                 const float* __restrict__ vw)
{
    int idx = blockIdx.x * blockDim.x + threadIdx.x;
    if (idx >= 2 * EMBED * EMBED) { return; }
    int w = idx >> 16;
    int rem = idx & 0xFFFF;
    int k = rem >> 8;
    int n = rem & 255;
    float x = (w ? vw : kw)[k * EMBED + n];
    __nv_bfloat16 h = __float2bfloat16(x);
    __nv_bfloat16 lo = __float2bfloat16(x - __bfloat162float(h));
    g_WTh[(w << 16) + n * EMBED + k] = h;
    g_WTl[(w << 16) + n * EMBED + k] = lo;
}

// ---------------------------------------------------------------------------
// convert active feature rows to compacted hi/lo bf16
// ---------------------------------------------------------------------------
__global__ __launch_bounds__(256) void convert_a_kernel(const float* __restrict__ fm)
{
    const int nact = g_nactive;
    int e4 = blockIdx.x * blockDim.x + threadIdx.x;
    int r = e4 >> 6;
    if (r >= nact) { return; }
    int c = (e4 & 63) * 4;
    const float4 v = *(const float4*)(fm + g_rows[r] * EMBED + c);
    float xs[4];
    xs[0] = v.x; xs[1] = v.y; xs[2] = v.z; xs[3] = v.w;
    __nv_bfloat16 hh[4];
    __nv_bfloat16 ll[4];
    for (int j = 0; j < 4; j++) {
        hh[j] = __float2bfloat16(xs[j]);
        ll[j] = __float2bfloat16(xs[j] - __bfloat162float(hh[j]));
    }
    *(uint2*)(g_Ah + r * EMBED + c) = *(uint2*)hh;
    *(uint2*)(g_Al + r * EMBED + c) = *(uint2*)ll;
}

// ---------------------------------------------------------------------------
// Kernel 1: LayerNorm + Q projection + RoPE.  4 queries per block.
// ---------------------------------------------------------------------------
__global__ __launch_bounds__(256) void qln_kernel(
    const float* __restrict__ query, const float* __restrict__ qpos,
    const float* __restrict__ nw, const float* __restrict__ nb,
    const float* __restrict__ qw, const float* __restrict__ rf, int n_q)
{
    const int t  = threadIdx.x;
    const int n0 = blockIdx.x * QR;
    __shared__ float xs[QR][EMBED];
    __shared__ float red[16];

    float val[QR];
    for (int r = 0; r < QR; r++) {
        int n = n0 + r;
        val[r] = (n < n_q) ? query[n * EMBED + t] : 0.f;
    }
    for (int r = 0; r < QR; r++) {
        float s = val[r], s2 = val[r] * val[r];
        for (int o = 16; o; o >>= 1) {
            s  += __shfl_xor_sync(~0u, s, o);
            s2 += __shfl_xor_sync(~0u, s2, o);
        }
        int w = t >> 5;
        if ((t & 31) == 0) { red[w] = s; red[8 + w] = s2; }
        __syncthreads();
        float sum = 0.f, sum2 = 0.f;
        for (int i = 0; i < 8; i++) { sum += red[i]; sum2 += red[8 + i]; }
        __syncthreads();
        float mean = sum * (1.0f / EMBED);
        float var  = sum2 * (1.0f / EMBED) - mean * mean;
        float inv  = rsqrtf(var + 1e-5f);
        xs[r][t] = (val[r] - mean) * inv * nw[t] + nb[t];
    }
    __syncthreads();

    float acc[QR];
    for (int r = 0; r < QR; r++) { acc[r] = 0.f; }
    #pragma unroll 8
    for (int i = 0; i < EMBED; i++) {
        float w = qw[i * EMBED + t];
        for (int r = 0; r < QR; r++) { acc[r] += xs[r][i] * w; }
    }
    __syncthreads();
    for (int r = 0; r < QR; r++) { xs[r][t] = acc[r]; }
    __syncthreads();

    const int p = (t & 31) >> 1;
    const float f0 = rf[p], f1 = rf[NPAIRS + p];
    for (int r = 0; r < QR; r++) {
        int n = n0 + r;
        if (n >= n_q) { break; }
        float ang = qpos[n * 2 + 0] * f0 + qpos[n * 2 + 1] * f1;
        float sn, cs;
        __sincosf(ang, &sn, &cs);
        float x1 = xs[r][t & ~1], x2 = xs[r][t | 1];
        g_qrot[n * EMBED + t] = ((t & 1) == 0) ? (x1 * cs - x2 * sn)
                                               : (x1 * sn + x2 * cs);
    }
}

// ---------------------------------------------------------------------------
// Kernel 2: tensor-core K/V GEMM over compacted rows (split bf16, 3 terms).
// Block: 64 rows x 128 cols. 8 warps as 2(m) x 4(n), warp tile 32x32.
// grid.x: bit1 = K/V weight, bit0 = col half. grid.y: row tiles.
// ---------------------------------------------------------------------------
__global__ __launch_bounds__(256) void kv_gemm_mma()
{
    const int nact = g_nactive;
    const int row0 = blockIdx.y * 64;
    if (row0 >= nact) { return; }

    const int bx   = blockIdx.x;
    const int wsel = (bx >> 1) & 1;
    float* outp    = wsel ? g_Vmap : g_Kmap;
    const int col0 = (bx & 1) * 128;

    __shared__ __nv_bfloat16 sAh[64 * GP];
    __shared__ __nv_bfloat16 sAl[64 * GP];
    __shared__ __nv_bfloat16 sBh[128 * GP];
    __shared__ __nv_bfloat16 sBl[128 * GP];
    __shared__ int sRow[64];

    const int tid = threadIdx.x;
    if (tid < 64) {
        int r = row0 + tid;
        sRow[tid] = (r < nact) ? g_rows[r] * EMBED : -1;
    }

    const int w    = tid >> 5;
    const int lane = tid & 31;
    const int mw   = (w & 1) * 32;
    const int nwp  = (w >> 1) * 32;

    float acc[2][4][4];
    for (int mi = 0; mi < 2; mi++) {
        for (int nj = 0; nj < 4; nj++) {
            for (int q = 0; q < 4; q++) { acc[mi][nj][q] = 0.f; }
        }
    }

    const int aRow = lane & 15;
    const int aK   = (lane >> 4) * 8;
    const int bRow = ((lane >> 4) << 3) + (lane & 7);
    const int bK   = ((lane >> 3) & 1) * 8;
    const unsigned baseAh = smem_u32(sAh);
    const unsigned baseAl = smem_u32(sAl);
    const unsigned baseBh = smem_u32(sBh);
    const unsigned baseBl = smem_u32(sBl);

    const __nv_bfloat16* WTh = g_WTh + (wsel << 16);
    const __nv_bfloat16* WTl = g_WTl + (wsel << 16);

    for (int kc = 0; kc < EMBED; kc += 32) {
        // A chunk: 64 rows x 32 k (hi+lo), uint2 = 4 bf16 per thread per iter
        #pragma unroll
        for (int i = 0; i < 2; i++) {
            int g4 = i * 256 + tid;
            int r  = g4 >> 3;
            int c4 = (g4 & 7) * 4;
            uint2 vh = make_uint2(0u, 0u);
            uint2 vl = make_uint2(0u, 0u);
            if (row0 + r < nact) {
                vh = *(const uint2*)(g_Ah + (row0 + r) * EMBED + kc + c4);
                vl = *(const uint2*)(g_Al + (row0 + r) * EMBED + kc + c4);
            }
            *(uint2*)&sAh[r * GP + c4] = vh;
            *(uint2*)&sAl[r * GP + c4] = vl;
        }
        // B chunk: 128 n-rows x 32 k, uint4 = 8 bf16
        #pragma unroll
        for (int i = 0; i < 2; i++) {
            int u4 = i * 256 + tid;
            int n  = u4 >> 2;
            int k8 = (u4 & 3) * 8;
            *(uint4*)&sBh[n * GP + k8] = *(const uint4*)(WTh + (col0 + n) * EMBED + kc + k8);
            *(uint4*)&sBl[n * GP + k8] = *(const uint4*)(WTl + (col0 + n) * EMBED + kc + k8);
        }
        __syncthreads();

        #pragma unroll
        for (int ks = 0; ks < 32; ks += 16) {
            unsigned ah[2][4];
            unsigned al[2][4];
            #pragma unroll
            for (int mi = 0; mi < 2; mi++) {
                unsigned off = (unsigned)(((mw + mi * 16 + aRow) * GP + ks + aK) * 2);
                ldm4(ah[mi], baseAh + off);
                ldm4(al[mi], baseAl + off);
            }
            #pragma unroll
            for (int ni = 0; ni < 2; ni++) {
                unsigned bh[4];
                unsigned bl[4];
                unsigned off = (unsigned)(((nwp + ni * 16 + bRow) * GP + ks + bK) * 2);
                ldm4(bh, baseBh + off);
                ldm4(bl, baseBl + off);
                #pragma unroll
                for (int mi = 0; mi < 2; mi++) {
                    mma16816(acc[mi][ni * 2],     ah[mi], bh);
                    mma16816(acc[mi][ni * 2 + 1], ah[mi], bh + 2);
                    mma16816(acc[mi][ni * 2],     ah[mi], bl);
                    mma16816(acc[mi][ni * 2 + 1], ah[mi], bl + 2);
                    mma16816(acc[mi][ni * 2],     al[mi], bh);
                    mma16816(acc[mi][ni * 2 + 1], al[mi], bh + 2);
                }
            }
        }
        __syncthreads();
    }

    // Epilogue: scatter C to padded map layout
    #pragma unroll
    for (int mi = 0; mi < 2; mi++) {
        int r0 = mw + mi * 16 + (lane >> 2);
        int ra = sRow[r0];
        int rb = sRow[r0 + 8];
        #pragma unroll
        for (int nj = 0; nj < 4; nj++) {
            int c = col0 + nwp + nj * 8 + (lane & 3) * 2;
            if (ra >= 0) {
                float2 v0;
                v0.x = acc[mi][nj][0];
                v0.y = acc[mi][nj][1];
                *(float2*)(outp + ra + c) = v0;
            }
            if (rb >= 0) {
                float2 v1;
                v1.x = acc[mi][nj][2];
                v1.y = acc[mi][nj][3];
                *(float2*)(outp + rb + c) = v1;
            }
        }
    }
}

// ---------------------------------------------------------------------------
// Kernel 3: attention. One block per query, 256 threads. Warp w == head w.
// ---------------------------------------------------------------------------
__global__ __launch_bounds__(256) void attn_kernel(const float* __restrict__ rf)
{
    const int n = blockIdx.x;
    const int t = threadIdx.x;

    __shared__ float F[48];
    __shared__ int   rowOff[KPQ];
    __shared__ float ksp0[KPQ];
    __shared__ float ksp1[KPQ];
    __shared__ float klvl[KPQ];
    __shared__ float csT[KPQ * NPAIRS];
    __shared__ float snT[KPQ * NPAIRS];
    __shared__ float logits[NHEADS * KPQ];

    if (t < 48) { F[t] = rf[t]; }
    if (t < KPQ) {
        rowOff[t] = g_rowOff[n * KPQ + t];
        ksp0[t]   = g_ksp0[n * KPQ + t];
        ksp1[t]   = g_ksp1[n * KPQ + t];
        int l;
        if      (t < 9)  { l = 0; }
        else if (t < 34) { l = 1; }
        else if (t < 83) { l = 2; }
        else             { l = 3; }
        klvl[t] = (float)l;
    }
    __syncthreads();

    for (int idx = t; idx < KPQ * NPAIRS; idx += 256) {
        int k = idx >> 4;
        int p = idx & 15;
        float ang = ksp0[k] * F[p] + ksp1[k] * F[NPAIRS + p] + klvl[k] * F[2 * NPAIRS + p];
        float sn, cs;
        __sincosf(ang, &sn, &cs);
        csT[idx] = cs;
        snT[idx] = sn;
    }
    __syncthreads();

    const int h = t >> 5;
    const int lane = t & 31;
    const int p = lane >> 1;
    const float qv = g_qrot[n * EMBED + t];
    const bool even = (lane & 1) == 0;

    for (int k = 0; k < KPQ; k++) {
        int ro = rowOff[k];
        if (ro >= 0) {
            float kv = g_Kmap[ro + t];
            float pn = __shfl_xor_sync(~0u, kv, 1);
            float cs = csT[k * NPAIRS + p];
            float sn = snT[k * NPAIRS + p];
            float kr = even ? (kv * cs - pn * sn) : (pn * sn + kv * cs);
            float c = qv * kr;
            for (int o = 16; o; o >>= 1) { c += __shfl_xor_sync(~0u, c, o); }
            if (lane == 0) { logits[h * KPQ + k] = c * 0.17677669529663687f; }
        } else {
            if (lane == 0) { logits[h * KPQ + k] = -1e9f; }
        }
    }
    __syncwarp();

    float m = -1e30f;
    for (int k = lane; k < KPQ; k += 32) { m = fmaxf(m, logits[h * KPQ + k]); }
    for (int o = 16; o; o >>= 1) { m = fmaxf(m, __shfl_xor_sync(~0u, m, o)); }
    float ssum = 0.f;
    for (int k = lane; k < KPQ; k += 32) {
        float e = __expf(logits[h * KPQ + k] - m);
        logits[h * KPQ + k] = e;
        ssum += e;
    }
    for (int o = 16; o; o >>= 1) { ssum += __shfl_xor_sync(~0u, ssum, o); }
    __syncwarp();
    const float inv = 1.0f / ssum;

    float acc = 0.f;
    for (int k = 0; k < KPQ; k++) {
        int ro = rowOff[k];
        if (ro >= 0) { acc += logits[h * KPQ + k] * g_Vmap[ro + t]; }
    }
    g_tmp[n * EMBED + t] = acc * inv;
}

// ---------------------------------------------------------------------------
// Kernel 4: output projection + residual.  4 queries per block.
// ---------------------------------------------------------------------------
__global__ __launch_bounds__(256) void out_proj_kernel(
    const float* __restrict__ query, const float* __restrict__ ow,
    float* __restrict__ out, int n_q)
{
    const int t  = threadIdx.x;
    const int n0 = blockIdx.x * QR;
    __shared__ float xs[QR][EMBED];

    for (int r = 0; r < QR; r++) {
        int n = n0 + r;
        xs[r][t] = (n < n_q) ? g_tmp[n * EMBED + t] : 0.f;
    }
    __syncthreads();

    float acc[QR];
    for (int r = 0; r < QR; r++) { acc[r] = 0.f; }
    #pragma unroll 8
    for (int i = 0; i < EMBED; i++) {
        float w = ow[i * EMBED + t];
        for (int r = 0; r < QR; r++) { acc[r] += xs[r][i] * w; }
    }
    for (int r = 0; r < QR; r++) {
        int n = n0 + r;
        if (n < n_q) { out[n * EMBED + t] = acc[r] + query[n * EMBED + t]; }
    }
}

// ---------------------------------------------------------------------------
extern "C" void kernel_launch(void* const* d_in, const int* in_sizes, int n_in,
                              void* d_out, int out_size)
{
    const float* query = (const float*)d_in[0];
    const float* qpos  = (const float*)d_in[1];
    const float* fm    = (const float*)d_in[2];
    const float* nw    = (const float*)d_in[3];
    const float* nb    = (const float*)d_in[4];
    const float* qw    = (const float*)d_in[5];
    const float* kw    = (const float*)d_in[6];
    const float* vw    = (const float*)d_in[7];
    const float* ow    = (const float*)d_in[8];
    const float* rf    = (const float*)d_in[9];
    const int*   boff  = (const int*)d_in[10];
    const int*   shp   = (const int*)d_in[11];

    int n_q   = in_sizes[0] / EMBED;
    int n_off = in_sizes[10];
    float* out = (float*)d_out;

    int qblocks = (n_q + QR - 1) / QR;
    zero_kernel<<<(NCELLS + 255) / 256, 256>>>();
    prep_kernel<<<n_q, 192>>>(qpos, boff, n_off, shp, n_q);
    compact_kernel<<<(NCELLS + 255) / 256, 256>>>();
    convert_w_kernel<<<(2 * EMBED * EMBED + 255) / 256, 256>>>(kw, vw);
    convert_a_kernel<<<(MAXROWS * 64 + 255) / 256, 256>>>(fm);
    qln_kernel<<<qblocks, 256>>>(query, qpos, nw, nb, qw, rf, n_q);
    kv_gemm_mma<<<dim3(4, (MAXROWS + 63) / 64), 256>>>();
    attn_kernel<<<n_q, 256>>>(rf);
    out_proj_kernel<<<qblocks, 256>>>(query, ow, out, n_q);
}

// round 14
// speedup vs baseline: 2.7530x; 1.2798x over previous
#include <cuda_runtime.h>
#include <cuda_bf16.h>
#include <cstdint>
#include <math.h>

#define EMBED   256
#define NHEADS  8
#define HDIM    32
#define NPAIRS  16
#define NLEV    4
#define FULL    128
#define KPQ     164
#define MAXQ    2048
#define MAXB    2
#define NCELLS  (MAXB * NLEV * FULL * FULL)
#define MAXROWS 43520
#define GP      40
#define QR      4

// Scratch (device globals; no runtime allocation allowed). 16B-aligned so
// float4/uint4 accesses are safe.
__device__ __align__(16) float g_Kmap[NCELLS * EMBED];
__device__ __align__(16) float g_Vmap[NCELLS * EMBED];
__device__ __align__(16) float g_qrot[MAXQ * EMBED];
__device__ __align__(16) float g_tmp [MAXQ * EMBED];
__device__ int   g_mask[NCELLS];
__device__ int   g_rows[NCELLS];
__device__ int   g_nactive;
__device__ int   g_rowOff[MAXQ * KPQ];
__device__ float g_ksp0[MAXQ * KPQ];
__device__ float g_ksp1[MAXQ * KPQ];
__device__ __align__(16) __nv_bfloat16 g_Ah[MAXROWS * EMBED];
__device__ __align__(16) __nv_bfloat16 g_Al[MAXROWS * EMBED];
__device__ __align__(16) __nv_bfloat16 g_WTh[2 * EMBED * EMBED];
__device__ __align__(16) __nv_bfloat16 g_WTl[2 * EMBED * EMBED];

// ---------------------------------------------------------------------------
// mma helpers
// ---------------------------------------------------------------------------
__device__ __forceinline__ unsigned smem_u32(const void* p)
{
    return (unsigned)__cvta_generic_to_shared(p);
}

__device__ __forceinline__ void ldm4(unsigned* r, unsigned a)
{
    asm volatile("ldmatrix.sync.aligned.m8n8.x4.shared.b16 {%0,%1,%2,%3}, [%4];"
        : "=r"(r[0]), "=r"(r[1]), "=r"(r[2]), "=r"(r[3]) : "r"(a));
}

__device__ __forceinline__ void mma16816(float* d, const unsigned* a, const unsigned* b)
{
    asm volatile("mma.sync.aligned.m16n8k16.row.col.f32.bf16.bf16.f32 "
        "{%0,%1,%2,%3}, {%4,%5,%6,%7}, {%8,%9}, {%0,%1,%2,%3};"
        : "+f"(d[0]), "+f"(d[1]), "+f"(d[2]), "+f"(d[3])
        : "r"(a[0]), "r"(a[1]), "r"(a[2]), "r"(a[3]), "r"(b[0]), "r"(b[1]));
}

// ---------------------------------------------------------------------------
__global__ void zero_kernel()
{
    int i = blockIdx.x * blockDim.x + threadIdx.x;
    if (i < NCELLS) { g_mask[i] = 0; }
    if (i == 0) { g_nactive = 0; }
}

// ---------------------------------------------------------------------------
__global__ void prep_kernel(const float* __restrict__ qpos,
                            const int* __restrict__ boff, int n_off,
                            const int* __restrict__ shp, int n_q)
{
    int n = blockIdx.x, t = threadIdx.x;
    if (n >= n_q || t >= KPQ) { return; }
    int l, base;
    if      (t < 9)  { l = 0; base = 0;  }
    else if (t < 34) { l = 1; base = 9;  }
    else if (t < 83) { l = 2; base = 34; }
    else             { l = 3; base = 83; }
    int s = 2 * l + 3, half = l + 1, j = t - base;
    int o0 = j / s - half, o1 = j % s - half;
    int H = shp[2 * l], W = shp[2 * l + 1];
    int maxH = 0, maxW = 0;
    for (int li = 0; li < NLEV; li++) {
        maxH = max(maxH, shp[2 * li]);
        maxW = max(maxW, shp[2 * li + 1]);
    }
    float p0 = qpos[n * 2 + 0], p1 = qpos[n * 2 + 1];
    int c0 = (int)floorf(p0 * ((float)H / (float)maxH));
    int c1 = (int)floorf(p1 * ((float)W / (float)maxW));
    int i0 = c0 + o0, i1 = c1 + o1;
    bool valid = (i0 >= 0) && (i0 < H) && (i1 >= 0) && (i1 < W);
    int b = 0;
    for (int ii = 1; ii < n_off - 1; ii++) {
        if (n >= boff[ii]) { b = ii; }
    }
    int cell = ((b * NLEV + l) * FULL + i0) * FULL + i1;
    g_rowOff[n * KPQ + t] = valid ? cell * EMBED : -1;
    if (valid) { g_mask[cell] = 1; }
    g_ksp0[n * KPQ + t] = (i0 + 0.5f) * ((float)maxH / (float)H);
    g_ksp1[n * KPQ + t] = (i1 + 0.5f) * ((float)maxW / (float)W);
}

// ---------------------------------------------------------------------------
__global__ void compact_kernel()
{
    int i = blockIdx.x * blockDim.x + threadIdx.x;
    if (i < NCELLS && g_mask[i]) {
        int p = atomicAdd(&g_nactive, 1);
        g_rows[p] = i;
    }
}

// ---------------------------------------------------------------------------
__global__ void convert_w_kernel(const float* __restrict__ kw,
                                 const float* __restrict__ vw)
{
    int idx = blockIdx.x * blockDim.x + threadIdx.x;
    if (idx >= 2 * EMBED * EMBED) { return; }
    int w = idx >> 16;
    int rem = idx & 0xFFFF;
    int k = rem >> 8;
    int n = rem & 255;
    float x = (w ? vw : kw)[k * EMBED + n];
    __nv_bfloat16 h = __float2bfloat16(x);
    __nv_bfloat16 lo = __float2bfloat16(x - __bfloat162float(h));
    g_WTh[(w << 16) + n * EMBED + k] = h;
    g_WTl[(w << 16) + n * EMBED + k] = lo;
}

// ---------------------------------------------------------------------------
__global__ __launch_bounds__(256) void convert_a_kernel(const float* __restrict__ fm)
{
    const int nact = g_nactive;
    int e4 = blockIdx.x * blockDim.x + threadIdx.x;
    int r = e4 >> 6;
    if (r >= nact) { return; }
    int c = (e4 & 63) * 4;
    const float4 v = *(const float4*)(fm + g_rows[r] * EMBED + c);
    float xs[4];
    xs[0] = v.x; xs[1] = v.y; xs[2] = v.z; xs[3] = v.w;
    __nv_bfloat16 hh[4];
    __nv_bfloat16 ll[4];
    for (int j = 0; j < 4; j++) {
        hh[j] = __float2bfloat16(xs[j]);
        ll[j] = __float2bfloat16(xs[j] - __bfloat162float(hh[j]));
    }
    *(uint2*)(g_Ah + r * EMBED + c) = *(uint2*)hh;
    *(uint2*)(g_Al + r * EMBED + c) = *(uint2*)ll;
}

// ---------------------------------------------------------------------------
// Kernel 1: LayerNorm + Q projection + RoPE.  4 queries per block.
// ---------------------------------------------------------------------------
__global__ __launch_bounds__(256) void qln_kernel(
    const float* __restrict__ query, const float* __restrict__ qpos,
    const float* __restrict__ nw, const float* __restrict__ nb,
    const float* __restrict__ qw, const float* __restrict__ rf, int n_q)
{
    const int t  = threadIdx.x;
    const int n0 = blockIdx.x * QR;
    __shared__ float xs[QR][EMBED];
    __shared__ float red[16];

    float val[QR];
    for (int r = 0; r < QR; r++) {
        int n = n0 + r;
        val[r] = (n < n_q) ? query[n * EMBED + t] : 0.f;
    }
    for (int r = 0; r < QR; r++) {
        float s = val[r], s2 = val[r] * val[r];
        for (int o = 16; o; o >>= 1) {
            s  += __shfl_xor_sync(~0u, s, o);
            s2 += __shfl_xor_sync(~0u, s2, o);
        }
        int w = t >> 5;
        if ((t & 31) == 0) { red[w] = s; red[8 + w] = s2; }
        __syncthreads();
        float sum = 0.f, sum2 = 0.f;
        for (int i = 0; i < 8; i++) { sum += red[i]; sum2 += red[8 + i]; }
        __syncthreads();
        float mean = sum * (1.0f / EMBED);
        float var  = sum2 * (1.0f / EMBED) - mean * mean;
        float inv  = rsqrtf(var + 1e-5f);
        xs[r][t] = (val[r] - mean) * inv * nw[t] + nb[t];
    }
    __syncthreads();

    float acc[QR];
    for (int r = 0; r < QR; r++) { acc[r] = 0.f; }
    #pragma unroll 8
    for (int i = 0; i < EMBED; i++) {
        float w = qw[i * EMBED + t];
        for (int r = 0; r < QR; r++) { acc[r] += xs[r][i] * w; }
    }
    __syncthreads();
    for (int r = 0; r < QR; r++) { xs[r][t] = acc[r]; }
    __syncthreads();

    const int p = (t & 31) >> 1;
    const float f0 = rf[p], f1 = rf[NPAIRS + p];
    for (int r = 0; r < QR; r++) {
        int n = n0 + r;
        if (n >= n_q) { break; }
        float ang = qpos[n * 2 + 0] * f0 + qpos[n * 2 + 1] * f1;
        float sn, cs;
        __sincosf(ang, &sn, &cs);
        float x1 = xs[r][t & ~1], x2 = xs[r][t | 1];
        g_qrot[n * EMBED + t] = ((t & 1) == 0) ? (x1 * cs - x2 * sn)
                                               : (x1 * sn + x2 * cs);
    }
}

// ---------------------------------------------------------------------------
// Kernel 2: tensor-core K/V GEMM over compacted rows (split bf16, 3 terms).
// Block: 64 rows x 128 cols. 8 warps as 2(m) x 4(n), warp tile 32x32.
// grid.x: bit1 = K/V weight, bit0 = col half. grid.y: row tiles.
// (Known-good R10 version: static smem, synchronous loads.)
// ---------------------------------------------------------------------------
__global__ __launch_bounds__(256) void kv_gemm_mma()
{
    const int nact = g_nactive;
    const int row0 = blockIdx.y * 64;
    if (row0 >= nact) { return; }

    const int bx   = blockIdx.x;
    const int wsel = (bx >> 1) & 1;
    float* outp    = wsel ? g_Vmap : g_Kmap;
    const int col0 = (bx & 1) * 128;

    __shared__ __nv_bfloat16 sAh[64 * GP];
    __shared__ __nv_bfloat16 sAl[64 * GP];
    __shared__ __nv_bfloat16 sBh[128 * GP];
    __shared__ __nv_bfloat16 sBl[128 * GP];
    __shared__ int sRow[64];

    const int tid = threadIdx.x;
    if (tid < 64) {
        int r = row0 + tid;
        sRow[tid] = (r < nact) ? g_rows[r] * EMBED : -1;
    }

    const int w    = tid >> 5;
    const int lane = tid & 31;
    const int mw   = (w & 1) * 32;
    const int nwp  = (w >> 1) * 32;

    float acc[2][4][4];
    for (int mi = 0; mi < 2; mi++) {
        for (int nj = 0; nj < 4; nj++) {
            for (int q = 0; q < 4; q++) { acc[mi][nj][q] = 0.f; }
        }
    }

    const int aRow = lane & 15;
    const int aK   = (lane >> 4) * 8;
    const int bRow = ((lane >> 4) << 3) + (lane & 7);
    const int bK   = ((lane >> 3) & 1) * 8;
    const unsigned baseAh = smem_u32(sAh);
    const unsigned baseAl = smem_u32(sAl);
    const unsigned baseBh = smem_u32(sBh);
    const unsigned baseBl = smem_u32(sBl);

    const __nv_bfloat16* WTh = g_WTh + (wsel << 16);
    const __nv_bfloat16* WTl = g_WTl + (wsel << 16);

    for (int kc = 0; kc < EMBED; kc += 32) {
        #pragma unroll
        for (int i = 0; i < 2; i++) {
            int g4 = i * 256 + tid;
            int r  = g4 >> 3;
            int c4 = (g4 & 7) * 4;
            uint2 vh = make_uint2(0u, 0u);
            uint2 vl = make_uint2(0u, 0u);
            if (row0 + r < nact) {
                vh = *(const uint2*)(g_Ah + (row0 + r) * EMBED + kc + c4);
                vl = *(const uint2*)(g_Al + (row0 + r) * EMBED + kc + c4);
            }
            *(uint2*)&sAh[r * GP + c4] = vh;
            *(uint2*)&sAl[r * GP + c4] = vl;
        }
        #pragma unroll
        for (int i = 0; i < 2; i++) {
            int u4 = i * 256 + tid;
            int n  = u4 >> 2;
            int k8 = (u4 & 3) * 8;
            *(uint4*)&sBh[n * GP + k8] = *(const uint4*)(WTh + (col0 + n) * EMBED + kc + k8);
            *(uint4*)&sBl[n * GP + k8] = *(const uint4*)(WTl + (col0 + n) * EMBED + kc + k8);
        }
        __syncthreads();

        #pragma unroll
        for (int ks = 0; ks < 32; ks += 16) {
            unsigned ah[2][4];
            unsigned al[2][4];
            #pragma unroll
            for (int mi = 0; mi < 2; mi++) {
                unsigned off = (unsigned)(((mw + mi * 16 + aRow) * GP + ks + aK) * 2);
                ldm4(ah[mi], baseAh + off);
                ldm4(al[mi], baseAl + off);
            }
            #pragma unroll
            for (int ni = 0; ni < 2; ni++) {
                unsigned bh[4];
                unsigned bl[4];
                unsigned off = (unsigned)(((nwp + ni * 16 + bRow) * GP + ks + bK) * 2);
                ldm4(bh, baseBh + off);
                ldm4(bl, baseBl + off);
                #pragma unroll
                for (int mi = 0; mi < 2; mi++) {
                    mma16816(acc[mi][ni * 2],     ah[mi], bh);
                    mma16816(acc[mi][ni * 2 + 1], ah[mi], bh + 2);
                    mma16816(acc[mi][ni * 2],     ah[mi], bl);
                    mma16816(acc[mi][ni * 2 + 1], ah[mi], bl + 2);
                    mma16816(acc[mi][ni * 2],     al[mi], bh);
                    mma16816(acc[mi][ni * 2 + 1], al[mi], bh + 2);
                }
            }
        }
        __syncthreads();
    }

    #pragma unroll
    for (int mi = 0; mi < 2; mi++) {
        int r0 = mw + mi * 16 + (lane >> 2);
        int ra = sRow[r0];
        int rb = sRow[r0 + 8];
        #pragma unroll
        for (int nj = 0; nj < 4; nj++) {
            int c = col0 + nwp + nj * 8 + (lane & 3) * 2;
            if (ra >= 0) {
                float2 v0;
                v0.x = acc[mi][nj][0];
                v0.y = acc[mi][nj][1];
                *(float2*)(outp + ra + c) = v0;
            }
            if (rb >= 0) {
                float2 v1;
                v1.x = acc[mi][nj][2];
                v1.y = acc[mi][nj][3];
                *(float2*)(outp + rb + c) = v1;
            }
        }
    }
}

// ---------------------------------------------------------------------------
// Kernel 3: attention. One block per query, 256 threads. Warp w == head w.
// Logit phase: 4 keys per warp concurrently, 8 lanes per key (float4 dims,
// self-contained RoPE pairs, 3-shuffle reduce).
// ---------------------------------------------------------------------------
__global__ __launch_bounds__(256) void attn_kernel(const float* __restrict__ rf)
{
    const int n = blockIdx.x;
    const int t = threadIdx.x;

    __shared__ float  F[48];
    __shared__ int    rowOff[KPQ];
    __shared__ float  ksp0[KPQ];
    __shared__ float  ksp1[KPQ];
    __shared__ float  klvl[KPQ];
    __shared__ float2 csn[KPQ * NPAIRS];
    __shared__ float  logits[NHEADS * KPQ];

    if (t < 48) { F[t] = rf[t]; }
    if (t < KPQ) {
        rowOff[t] = g_rowOff[n * KPQ + t];
        ksp0[t]   = g_ksp0[n * KPQ + t];
        ksp1[t]   = g_ksp1[n * KPQ + t];
        int l;
        if      (t < 9)  { l = 0; }
        else if (t < 34) { l = 1; }
        else if (t < 83) { l = 2; }
        else             { l = 3; }
        klvl[t] = (float)l;
    }
    __syncthreads();

    for (int idx = t; idx < KPQ * NPAIRS; idx += 256) {
        int k = idx >> 4;
        int p = idx & 15;
        float ang = ksp0[k] * F[p] + ksp1[k] * F[NPAIRS + p] + klvl[k] * F[2 * NPAIRS + p];
        float sn, cs;
        __sincosf(ang, &sn, &cs);
        csn[idx] = make_float2(cs, sn);
    }
    __syncthreads();

    const int h    = t >> 5;
    const int lane = t & 31;
    const int grp  = lane >> 3;   // 0..3: which key in the 4-key group
    const int sub  = lane & 7;    // 0..7: dim quad within the head

    const float4 q4 = *(const float4*)(g_qrot + n * EMBED + h * HDIM + sub * 4);

    for (int kb = 0; kb < KPQ; kb += 4) {
        int k  = kb + grp;
        int ro = rowOff[k];
        float c = 0.f;
        if (ro >= 0) {
            float4 kv = *(const float4*)(g_Kmap + ro + h * HDIM + sub * 4);
            float2 cs0 = csn[k * NPAIRS + sub * 2];
            float2 cs1 = csn[k * NPAIRS + sub * 2 + 1];
            float r0 = kv.x * cs0.x - kv.y * cs0.y;
            float r1 = kv.x * cs0.y + kv.y * cs0.x;
            float r2 = kv.z * cs1.x - kv.w * cs1.y;
            float r3 = kv.z * cs1.y + kv.w * cs1.x;
            c = q4.x * r0 + q4.y * r1 + q4.z * r2 + q4.w * r3;
        }
        c += __shfl_xor_sync(~0u, c, 1);
        c += __shfl_xor_sync(~0u, c, 2);
        c += __shfl_xor_sync(~0u, c, 4);
        if (sub == 0) {
            logits[h * KPQ + k] = (ro >= 0) ? c * 0.17677669529663687f : -1e9f;
        }
    }
    __syncwarp();

    float m = -1e30f;
    for (int k = lane; k < KPQ; k += 32) { m = fmaxf(m, logits[h * KPQ + k]); }
    for (int o = 16; o; o >>= 1) { m = fmaxf(m, __shfl_xor_sync(~0u, m, o)); }
    float ssum = 0.f;
    for (int k = lane; k < KPQ; k += 32) {
        float e = __expf(logits[h * KPQ + k] - m);
        logits[h * KPQ + k] = e;
        ssum += e;
    }
    for (int o = 16; o; o >>= 1) { ssum += __shfl_xor_sync(~0u, ssum, o); }
    __syncwarp();
    const float inv = 1.0f / ssum;

    float acc = 0.f;
    for (int k = 0; k < KPQ; k++) {
        int ro = rowOff[k];
        if (ro >= 0) { acc += logits[h * KPQ + k] * g_Vmap[ro + t]; }
    }
    g_tmp[n * EMBED + t] = acc * inv;
}

// ---------------------------------------------------------------------------
// Kernel 4: output projection + residual.  4 queries per block.
// ---------------------------------------------------------------------------
__global__ __launch_bounds__(256) void out_proj_kernel(
    const float* __restrict__ query, const float* __restrict__ ow,
    float* __restrict__ out, int n_q)
{
    const int t  = threadIdx.x;
    const int n0 = blockIdx.x * QR;
    __shared__ float xs[QR][EMBED];

    for (int r = 0; r < QR; r++) {
        int n = n0 + r;
        xs[r][t] = (n < n_q) ? g_tmp[n * EMBED + t] : 0.f;
    }
    __syncthreads();

    float acc[QR];
    for (int r = 0; r < QR; r++) { acc[r] = 0.f; }
    #pragma unroll 8
    for (int i = 0; i < EMBED; i++) {
        float w = ow[i * EMBED + t];
        for (int r = 0; r < QR; r++) { acc[r] += xs[r][i] * w; }
    }
    for (int r = 0; r < QR; r++) {
        int n = n0 + r;
        if (n < n_q) { out[n * EMBED + t] = acc[r] + query[n * EMBED + t]; }
    }
}

// ---------------------------------------------------------------------------
extern "C" void kernel_launch(void* const* d_in, const int* in_sizes, int n_in,
                              void* d_out, int out_size)
{
    const float* query = (const float*)d_in[0];
    const float* qpos  = (const float*)d_in[1];
    const float* fm    = (const float*)d_in[2];
    const float* nw    = (const float*)d_in[3];
    const float* nb    = (const float*)d_in[4];
    const float* qw    = (const float*)d_in[5];
    const float* kw    = (const float*)d_in[6];
    const float* vw    = (const float*)d_in[7];
    const float* ow    = (const float*)d_in[8];
    const float* rf    = (const float*)d_in[9];
    const int*   boff  = (const int*)d_in[10];
    const int*   shp   = (const int*)d_in[11];

    int n_q   = in_sizes[0] / EMBED;
    int n_off = in_sizes[10];
    float* out = (float*)d_out;

    int qblocks = (n_q + QR - 1) / QR;
    zero_kernel<<<(NCELLS + 255) / 256, 256>>>();
    prep_kernel<<<n_q, 192>>>(qpos, boff, n_off, shp, n_q);
    compact_kernel<<<(NCELLS + 255) / 256, 256>>>();
    convert_w_kernel<<<(2 * EMBED * EMBED + 255) / 256, 256>>>(kw, vw);
    convert_a_kernel<<<(MAXROWS * 64 + 255) / 256, 256>>>(fm);
    qln_kernel<<<qblocks, 256>>>(query, qpos, nw, nb, qw, rf, n_q);
    kv_gemm_mma<<<dim3(4, (MAXROWS + 63) / 64), 256>>>();
    attn_kernel<<<n_q, 256>>>(rf);
    out_proj_kernel<<<qblocks, 256>>>(query, ow, out, n_q);
}